// round 6
// baseline (speedup 1.0000x reference)
#include <cuda_runtime.h>
#include <cstdint>

// Problem constants (D=20, RANK=2 -> o=19 per axis, m=32)
#define O      19
#define DM     20
#define MM     32
#define NT     320                   // 10 warps per CTA, 2 CTAs per SM
#define NWARP  10
#define NITEMS (O*O*4)               // (a,b) x d-quint  = 1444

typedef unsigned long long ull;

// ---- packed f32x2 helpers ----
__device__ __forceinline__ ull f2mul(ull a, ull b) {
    ull r; asm("mul.rn.f32x2 %0, %1, %2;" : "=l"(r) : "l"(a), "l"(b)); return r;
}
__device__ __forceinline__ ull f2fma(ull a, ull b, ull c) {
    ull r; asm("fma.rn.f32x2 %0, %1, %2, %3;" : "=l"(r) : "l"(a), "l"(b), "l"(c)); return r;
}
__device__ __forceinline__ float f2sum(ull v) {
    return __uint_as_float((unsigned)v) + __uint_as_float((unsigned)(v >> 32));
}

// Shared memory layout (floats):
//   Ct  [19][32][32] @ 0      (19456)  XOR-swizzled: chunk q_phys = (j>>2)^(i&7)
//   R'  [20][6][32]  @ 19456  (3840)   (a,b)-pair sums, d-slice rows
//   X   [19][5][32]  @ 23296  (3040)   x[c, dd, j]
//   WS  [10][32]     @ 26336  (320)    per-warp staging
#define CT_OFF   0
#define R_OFF    19456
#define X_OFF    23296
#define WS_OFF   26336
#define SMEM_FLOATS 26656
#define SMEM_BYTES (SMEM_FLOATS * 4)    // 106624 B -> 2 CTAs/SM

__global__ void __launch_bounds__(NT, 2)
pm4_kernel(const float* __restrict__ H,   // [20,20,20,20,32]
           const float* __restrict__ Mw,  // [32,32]
           const float* __restrict__ P,   // [32,32]
           float* __restrict__ out)       // [19^4, 32]
{
    extern __shared__ float s[];
    float* Ct  = s + CT_OFF;
    float* R   = s + R_OFF;
    float* X   = s + X_OFF;
    float* WSs = s + WS_OFF;

    const int tid  = threadIdx.x;
    const int lane = tid & 31;
    const int w    = tid >> 5;        // warp = c-pair 0..9
    const int c0   = 2 * w;
    const int nc   = (w == 9) ? 1 : 2;
    const int c1   = (nc == 2) ? c0 + 1 : c0;
    const int g    = gridDim.x;
    const int m7   = lane & 7;        // swizzle key

    const float TWO_PI = 6.28318530717958647692f;

    // ---- once per CTA: swizzled cos table ----
    for (int e = tid; e < O * MM * MM; e += NT) {
        int n = e >> 10;
        int r = e & 1023;
        int i = r >> 5;
        int j = r & 31;
        float per = (float)(i * MM + j + 2);
        int qp = ((j >> 2) ^ (i & 7));         // physical chunk
        Ct[n * 1024 + i * 32 + qp * 4 + (j & 3)] = cosf(TWO_PI * (float)n / per);
    }

    float* wsp = WSs + w * 32;

    for (int item = blockIdx.x; item < NITEMS; item += g) {
        const int ab = item >> 2;
        const int q  = item & 3;
        const int A  = ab / O;
        const int B  = ab % O;
        const int dstart = 5 * q;
        const int dnum   = (q == 3) ? 4 : 5;
        const int rows   = dnum + 1;          // R' rows needed

        __syncthreads();   // previous item fully consumed R'/X (also covers Ct build)

        // ---- R' = 2x2 (a,b) pair-sum for d-rows [dstart, dstart+rows) ----
        {
            const int strideB = DM * DM * MM;      // 12800 floats
            const int strideA = DM * strideB;
            const float4* H00 = (const float4*)(H + (long)A * strideA + (long)B * strideB);
            const float4* H01 = H00 + strideB / 4;
            const float4* H10 = H00 + strideA / 4;
            const float4* H11 = H10 + strideB / 4;
            const int total4 = DM * rows * 8;      // <= 960
            int gidx[3], sidx[3];
            float4 pa[3], pb[3], acc[3];
            int cnt = 0;
            #pragma unroll
            for (int k = 0; k < 3; k++) {
                int e = tid + k * NT;
                if (e < total4) {
                    int c  = e / (rows * 8);
                    int rm = e - c * rows * 8;
                    int dr = rm >> 3;
                    int f  = rm & 7;
                    gidx[k] = (c * DM + dstart + dr) * 8 + f;
                    sidx[k] = (c * 6 + dr) * 8 + f;
                    cnt = k + 1;
                }
            }
            #pragma unroll
            for (int k = 0; k < 3; k++) if (k < cnt) { pa[k] = H00[gidx[k]]; pb[k] = H01[gidx[k]]; }
            #pragma unroll
            for (int k = 0; k < 3; k++) if (k < cnt)
                acc[k] = make_float4(pa[k].x + pb[k].x, pa[k].y + pb[k].y,
                                     pa[k].z + pb[k].z, pa[k].w + pb[k].w);
            #pragma unroll
            for (int k = 0; k < 3; k++) if (k < cnt) { pa[k] = H10[gidx[k]]; pb[k] = H11[gidx[k]]; }
            float4* R4 = (float4*)R;
            #pragma unroll
            for (int k = 0; k < 3; k++) if (k < cnt)
                R4[sidx[k]] = make_float4(acc[k].x + pa[k].x + pb[k].x,
                                          acc[k].y + pa[k].y + pb[k].y,
                                          acc[k].z + pa[k].z + pb[k].z,
                                          acc[k].w + pa[k].w + pb[k].w);
        }
        __syncthreads();   // R' ready

        // ---- Phase P: window sums + matvec -> X[c][dd][j] (lane = j) ----
        {
            // M row from global (L1-hot), prescaled 1/16
            ull Mreg[16];
            {
                const ulonglong2* mr = (const ulonglong2*)(Mw + lane * MM);
                const ull sc = (ull)__float_as_uint(0.0625f) | ((ull)__float_as_uint(0.0625f) << 32);
                #pragma unroll
                for (int k = 0; k < 8; k++) {
                    ulonglong2 m = mr[k];
                    Mreg[2 * k]     = f2mul(m.x, sc);
                    Mreg[2 * k + 1] = f2mul(m.y, sc);
                }
            }
            const int npairs = O * dnum;
            #pragma unroll 1
            for (int p = w; p < npairs; p += NWARP) {
                const int c  = p / dnum;
                const int dd = p - c * dnum;
                const float* r0 = &R[(c * 6 + dd) * MM + lane];
                float v = (r0[0] + r0[MM]) + (r0[6 * MM] + r0[7 * MM]);
                wsp[lane] = v;
                __syncwarp();
                ull a0 = 0, a1 = 0;
                #pragma unroll
                for (int l4 = 0; l4 < 8; l4++) {
                    ulonglong2 wv = *reinterpret_cast<const ulonglong2*>(&wsp[4 * l4]);
                    a0 = f2fma(Mreg[2 * l4],     wv.x, a0);
                    a1 = f2fma(Mreg[2 * l4 + 1], wv.y, a1);
                }
                X[(c * 5 + dd) * 32 + lane] = f2sum(a0) + f2sum(a1);
                __syncwarp();
            }
        }

        // ---- G = P * Ct[A] * Ct[B] * Ct[c] in registers (overlaps barrier wait) ----
        ull G0[16], G1[16];
        {
            const float* ca = &Ct[A  * 1024 + lane * 32];
            const float* cb = &Ct[B  * 1024 + lane * 32];
            const float* cc = &Ct[c0 * 1024 + lane * 32];
            const float* cd = &Ct[c1 * 1024 + lane * 32];
            const float* pr = P + lane * MM;
            #pragma unroll
            for (int l = 0; l < 8; l++) {
                const int qp = (l ^ m7) * 4;                    // physical chunk offset
                ulonglong2 av = *reinterpret_cast<const ulonglong2*>(ca + qp);
                ulonglong2 bv = *reinterpret_cast<const ulonglong2*>(cb + qp);
                ulonglong2 pv = *reinterpret_cast<const ulonglong2*>(pr + 4 * l);  // logical
                ull gx = f2mul(f2mul(pv.x, av.x), bv.x);
                ull gy = f2mul(f2mul(pv.y, av.y), bv.y);
                ulonglong2 cv = *reinterpret_cast<const ulonglong2*>(cc + qp);
                ulonglong2 dv = *reinterpret_cast<const ulonglong2*>(cd + qp);
                G0[2 * l]     = f2mul(gx, cv.x);
                G0[2 * l + 1] = f2mul(gy, cv.y);
                G1[2 * l]     = f2mul(gx, dv.x);
                G1[2 * l + 1] = f2mul(gy, dv.y);
            }
        }
        __syncthreads();   // X ready

        // ---- Phase C: warp = c-pair, lane = i, loop dd (staggered) ----
        {
            const int outBase = ab * (O * O) * MM;
            const int st = w % dnum;
            #pragma unroll 1
            for (int t = 0; t < dnum; t++) {
                int dd = st + t; if (dd >= dnum) dd -= dnum;
                const int d = dstart + dd;
                const float* cdr  = &Ct[d * 1024 + lane * 32];
                const float* xv0p = &X[(c0 * 5 + dd) * 32];
                const float* xv1p = &X[(c1 * 5 + dd) * 32];
                ull A0 = 0, A0b = 0, A1 = 0, A1b = 0;
                #pragma unroll
                for (int l = 0; l < 8; l++) {
                    const int qp = (l ^ m7) * 4;
                    ulonglong2 cd  = *reinterpret_cast<const ulonglong2*>(cdr + qp);
                    ulonglong2 xv0 = *reinterpret_cast<const ulonglong2*>(xv0p + 4 * l);
                    ulonglong2 xv1 = *reinterpret_cast<const ulonglong2*>(xv1p + 4 * l);
                    A0  = f2fma(f2mul(cd.x, G0[2 * l]),     xv0.x, A0);
                    A0b = f2fma(f2mul(cd.y, G0[2 * l + 1]), xv0.y, A0b);
                    A1  = f2fma(f2mul(cd.x, G1[2 * l]),     xv1.x, A1);
                    A1b = f2fma(f2mul(cd.y, G1[2 * l + 1]), xv1.y, A1b);
                }
                out[outBase + (c0 * O + d) * MM + lane] = f2sum(A0) + f2sum(A0b);
                if (nc == 2)
                    out[outBase + (c1 * O + d) * MM + lane] = f2sum(A1) + f2sum(A1b);
            }
        }
    }
}

extern "C" void kernel_launch(void* const* d_in, const int* in_sizes, int n_in,
                              void* d_out, int out_size)
{
    const float* H  = (const float*)d_in[0];
    const float* Mw = (const float*)d_in[1];
    const float* P  = (const float*)d_in[2];
    float* out = (float*)d_out;

    cudaFuncSetAttribute(pm4_kernel, cudaFuncAttributeMaxDynamicSharedMemorySize, SMEM_BYTES);

    int dev = 0, nsm = 148;
    cudaGetDevice(&dev);
    cudaDeviceGetAttribute(&nsm, cudaDevAttrMultiProcessorCount, dev);
    if (nsm <= 0) nsm = 148;
    int grid = 2 * nsm;
    if (grid > NITEMS) grid = NITEMS;

    pm4_kernel<<<grid, NT, SMEM_BYTES>>>(H, Mw, P, out);
}